// round 1
// baseline (speedup 1.0000x reference)
#include <cuda_runtime.h>

#define BB 2
#define SS 2048
#define EE 512
#define HH 8
#define DD 64
#define MT (BB*SS)   // 4096 rows total

// Scratch (device globals: allocation-free per harness rules)
__device__ float g_P [MT*EE];
__device__ float g_C [MT*EE];
__device__ float g_Sv[MT*EE];
__device__ float g_AO[MT*EE];

// ---------------------------------------------------------------------------
// Tiled SGEMM with bias:  Out[M,N] = A[M,K] @ W[K,N] + bias[N]
// BM=BN=64, BK=16, 256 threads, 4x4 per thread.
// ---------------------------------------------------------------------------
__global__ __launch_bounds__(256) void gemm_bias64(
    const float* __restrict__ A, const float* __restrict__ W,
    const float* __restrict__ bias, float* __restrict__ Out,
    int M, int N, int K)
{
    __shared__ float As[16][64];   // [k][m] (transposed store)
    __shared__ float Bs[16][64];   // [k][n]

    const int t  = threadIdx.x;
    const int bm = blockIdx.y * 64;
    const int bn = blockIdx.x * 64;
    const int tx = t & 15;          // col group
    const int ty = t >> 4;          // row group
    const int aRow = t >> 2;        // 0..63
    const int aCol = (t & 3) << 2;  // 0,4,8,12
    const int bRow = t >> 4;        // 0..15
    const int bCol = (t & 15) << 2; // 0..60

    float acc[4][4] = {};

    for (int k0 = 0; k0 < K; k0 += 16) {
        float4 av = *reinterpret_cast<const float4*>(
            A + (size_t)(bm + aRow) * K + k0 + aCol);
        As[aCol+0][aRow] = av.x;
        As[aCol+1][aRow] = av.y;
        As[aCol+2][aRow] = av.z;
        As[aCol+3][aRow] = av.w;
        float4 wv = *reinterpret_cast<const float4*>(
            W + (size_t)(k0 + bRow) * N + bn + bCol);
        *reinterpret_cast<float4*>(&Bs[bRow][bCol]) = wv;
        __syncthreads();

        #pragma unroll
        for (int k = 0; k < 16; k++) {
            float4 ra = *reinterpret_cast<const float4*>(&As[k][ty << 2]);
            float4 rb = *reinterpret_cast<const float4*>(&Bs[k][tx << 2]);
            float a_[4] = {ra.x, ra.y, ra.z, ra.w};
            float b_[4] = {rb.x, rb.y, rb.z, rb.w};
            #pragma unroll
            for (int i = 0; i < 4; i++)
                #pragma unroll
                for (int j = 0; j < 4; j++)
                    acc[i][j] = fmaf(a_[i], b_[j], acc[i][j]);
        }
        __syncthreads();
    }

    float4 bv = *reinterpret_cast<const float4*>(bias + bn + (tx << 2));
    const float bb[4] = {bv.x, bv.y, bv.z, bv.w};
    #pragma unroll
    for (int i = 0; i < 4; i++) {
        int row = bm + (ty << 2) + i;
        float4 o;
        o.x = acc[i][0] + bb[0];
        o.y = acc[i][1] + bb[1];
        o.z = acc[i][2] + bb[2];
        o.w = acc[i][3] + bb[3];
        *reinterpret_cast<float4*>(Out + (size_t)row * N + bn + (tx << 2)) = o;
    }
}

// ---------------------------------------------------------------------------
// Sparse tree attention.
// One block per (b, n). Warp 0 builds the ordered neighbor list (ballot
// prefix — deterministic, ascending m). Then warp h (h = 0..7) does an
// online-softmax over the neighbors for head h and writes AO[b,n,h,:].
// Neighbors of n: {parent[n]} ∪ {m : parent[m] == n}. Always >= 1 entry.
// ---------------------------------------------------------------------------
__global__ __launch_bounds__(256) void tree_attn(const int* __restrict__ parent)
{
    const int bn = blockIdx.x;           // 0..MT-1
    const int b  = bn / SS;
    const int n  = bn % SS;

    __shared__ int list[SS];
    __shared__ int cnt;

    const int t    = threadIdx.x;
    const int warp = t >> 5;
    const int lane = t & 31;

    const int par_n = parent[b * SS + n];

    if (warp == 0) {
        int base = 0;
        for (int m0 = 0; m0 < SS; m0 += 32) {
            int m = m0 + lane;
            bool pred = (m == par_n) || (parent[b * SS + m] == n);
            unsigned bal = __ballot_sync(0xffffffffu, pred);
            int pos = __popc(bal & ((1u << lane) - 1u));
            if (pred) list[base + pos] = m;
            base += __popc(bal);
        }
        if (lane == 0) cnt = base;
    }
    __syncthreads();

    const int count = cnt;

    // head = warp; each lane holds dims (lane, lane+32)
    const float* Prow = &g_P[(size_t)bn * EE + warp * DD];
    const float p0 = Prow[lane];
    const float p1 = Prow[lane + 32];

    float m_run = -1e30f, l_run = 0.0f, a0 = 0.0f, a1 = 0.0f;
    const float scale = 0.125f;  // 1/sqrt(64)

    for (int i = 0; i < count; i++) {
        int m = list[i];
        const size_t mrow = ((size_t)b * SS + m) * EE + warp * DD;
        const float* Crow = &g_C[mrow];
        float part = p0 * Crow[lane] + p1 * Crow[lane + 32];
        #pragma unroll
        for (int off = 16; off; off >>= 1)
            part += __shfl_xor_sync(0xffffffffu, part, off);
        float scr = part * scale;

        float m_new = fmaxf(m_run, scr);
        float corr  = __expf(m_run - m_new);
        float w     = __expf(scr - m_new);
        const float* Srow = &g_Sv[mrow];
        a0 = a0 * corr + w * Srow[lane];
        a1 = a1 * corr + w * Srow[lane + 32];
        l_run = l_run * corr + w;
        m_run = m_new;
    }

    const float inv = 1.0f / l_run;
    float* Orow = &g_AO[(size_t)bn * EE + warp * DD];
    Orow[lane]      = a0 * inv;
    Orow[lane + 32] = a1 * inv;
}

// ---------------------------------------------------------------------------
extern "C" void kernel_launch(void* const* d_in, const int* in_sizes, int n_in,
                              void* d_out, int out_size)
{
    (void)in_sizes; (void)n_in; (void)out_size;
    const float* x      = (const float*)d_in[0];
    const int*   parent = (const int*)  d_in[1];
    const float* Wp = (const float*)d_in[2];
    const float* bp = (const float*)d_in[3];
    const float* Wc = (const float*)d_in[4];
    const float* bc = (const float*)d_in[5];
    const float* Ws = (const float*)d_in[6];
    const float* bs = (const float*)d_in[7];
    const float* Wo = (const float*)d_in[8];
    const float* bo = (const float*)d_in[9];
    float* out = (float*)d_out;

    float *P, *C, *Sv, *AO;
    cudaGetSymbolAddress((void**)&P,  g_P);
    cudaGetSymbolAddress((void**)&C,  g_C);
    cudaGetSymbolAddress((void**)&Sv, g_Sv);
    cudaGetSymbolAddress((void**)&AO, g_AO);

    dim3 grid(EE / 64, MT / 64);   // (8, 64) = 512 blocks
    gemm_bias64<<<grid, 256>>>(x,  Wp, bp, P,   MT, EE, EE);
    gemm_bias64<<<grid, 256>>>(x,  Wc, bc, C,   MT, EE, EE);
    gemm_bias64<<<grid, 256>>>(x,  Ws, bs, Sv,  MT, EE, EE);
    tree_attn<<<MT, 256>>>(parent);
    gemm_bias64<<<grid, 256>>>(AO, Wo, bo, out, MT, EE, EE);
}

// round 3
// speedup vs baseline: 2.0653x; 2.0653x over previous
#include <cuda_runtime.h>
#include <cuda_bf16.h>
#include <cstdint>

#define BB 2
#define SS 2048
#define EE 512
#define HH 8
#define DD 64
#define MT (BB*SS)   // 4096 rows total

// ---------------------------------------------------------------------------
// Scratch (device globals: allocation-free per harness rules)
// ---------------------------------------------------------------------------
__device__ float g_P [MT*EE];
__device__ float g_C [MT*EE];
__device__ float g_Sv[MT*EE];
__device__ float g_AO[MT*EE];

__device__ __align__(16) __nv_bfloat16 g_xh [MT*EE];
__device__ __align__(16) __nv_bfloat16 g_xl [MT*EE];
__device__ __align__(16) __nv_bfloat16 g_aoh[MT*EE];
__device__ __align__(16) __nv_bfloat16 g_aol[MT*EE];
// transposed weights [N=512][K=512], hi/lo
__device__ __align__(16) __nv_bfloat16 g_Wth[4][EE*EE];
__device__ __align__(16) __nv_bfloat16 g_Wtl[4][EE*EE];

// ---------------------------------------------------------------------------
// Helpers (base-target PTX only: ldmatrix / mma.sync / cp.async)
// ---------------------------------------------------------------------------
__device__ __forceinline__ uint32_t smem_u32(const void* p) {
    uint32_t a;
    asm("{ .reg .u64 t; cvta.to.shared.u64 t, %1; cvt.u32.u64 %0, t; }"
        : "=r"(a) : "l"(p));
    return a;
}

__device__ __forceinline__ void ldsm4(uint32_t* r, uint32_t addr) {
    asm volatile("ldmatrix.sync.aligned.m8n8.x4.shared.b16 {%0,%1,%2,%3}, [%4];"
        : "=r"(r[0]), "=r"(r[1]), "=r"(r[2]), "=r"(r[3]) : "r"(addr));
}

__device__ __forceinline__ void mma16816(float* d, const uint32_t* a,
                                         uint32_t b0, uint32_t b1) {
    asm volatile("mma.sync.aligned.m16n8k16.row.col.f32.bf16.bf16.f32 "
        "{%0,%1,%2,%3}, {%4,%5,%6,%7}, {%8,%9}, {%0,%1,%2,%3};"
        : "+f"(d[0]), "+f"(d[1]), "+f"(d[2]), "+f"(d[3])
        : "r"(a[0]), "r"(a[1]), "r"(a[2]), "r"(a[3]), "r"(b0), "r"(b1));
}

__device__ __forceinline__ void cpasync16(uint32_t saddr, const void* g) {
    asm volatile("cp.async.cg.shared.global [%0], [%1], 16;"
                 :: "r"(saddr), "l"(g) : "memory");
}
#define CP_COMMIT() asm volatile("cp.async.commit_group;" ::: "memory")
#define CP_WAIT(n)  asm volatile("cp.async.wait_group %0;" :: "n"(n) : "memory")

// ---------------------------------------------------------------------------
// Split fp32 -> (hi, lo) bf16. n4 = element_count/4.
// ---------------------------------------------------------------------------
__global__ __launch_bounds__(256) void split_f32(
    const float* __restrict__ in, __nv_bfloat16* __restrict__ hi,
    __nv_bfloat16* __restrict__ lo, int n4)
{
    int i = blockIdx.x * 256 + threadIdx.x;
    if (i >= n4) return;
    float4 v = reinterpret_cast<const float4*>(in)[i];
    __nv_bfloat16 h0 = __float2bfloat16_rn(v.x);
    __nv_bfloat16 h1 = __float2bfloat16_rn(v.y);
    __nv_bfloat16 h2 = __float2bfloat16_rn(v.z);
    __nv_bfloat16 h3 = __float2bfloat16_rn(v.w);
    __nv_bfloat16 l0 = __float2bfloat16_rn(v.x - __bfloat162float(h0));
    __nv_bfloat16 l1 = __float2bfloat16_rn(v.y - __bfloat162float(h1));
    __nv_bfloat16 l2 = __float2bfloat16_rn(v.z - __bfloat162float(h2));
    __nv_bfloat16 l3 = __float2bfloat16_rn(v.w - __bfloat162float(h3));
    reinterpret_cast<__nv_bfloat162*>(hi)[i*2+0] = __nv_bfloat162(h0, h1);
    reinterpret_cast<__nv_bfloat162*>(hi)[i*2+1] = __nv_bfloat162(h2, h3);
    reinterpret_cast<__nv_bfloat162*>(lo)[i*2+0] = __nv_bfloat162(l0, l1);
    reinterpret_cast<__nv_bfloat162*>(lo)[i*2+1] = __nv_bfloat162(l2, l3);
}

// ---------------------------------------------------------------------------
// Transpose + split one 512x512 weight: Wt[n][k] = W[k][n], hi/lo bf16.
// block (32,8), grid (16,16)
// ---------------------------------------------------------------------------
__global__ __launch_bounds__(256) void wsplit_t(
    const float* __restrict__ W, __nv_bfloat16* __restrict__ th,
    __nv_bfloat16* __restrict__ tl)
{
    __shared__ float t[32][33];
    const int k0 = blockIdx.x * 32, n0 = blockIdx.y * 32;
    const int tx = threadIdx.x;
    for (int j = threadIdx.y; j < 32; j += 8)
        t[j][tx] = W[(size_t)(k0 + j) * EE + n0 + tx];
    __syncthreads();
    for (int j = threadIdx.y; j < 32; j += 8) {
        float v = t[tx][j];
        __nv_bfloat16 h = __float2bfloat16_rn(v);
        __nv_bfloat16 l = __float2bfloat16_rn(v - __bfloat162float(h));
        th[(size_t)(n0 + j) * EE + k0 + tx] = h;
        tl[(size_t)(n0 + j) * EE + k0 + tx] = l;
    }
}

// ---------------------------------------------------------------------------
// mma.sync split-bf16 GEMM: Out[M,512] = A[M,512] @ W[512,512] + bias
// A as (Ah, Al) bf16 K-major [M][512]; W transposed (Bh, Bl)[N=512][K=512].
// CTA 128x128, 8 warps (2 M x 4 N), warp tile 64x32.
// K-chunks of 32, cp.async double buffer.
// smem tile: 128 rows x 80B pitch (32 bf16 used) -> conflict-free ldmatrix.
// ---------------------------------------------------------------------------
#define PITCHB   80
#define TILE_B   (128 * PITCHB)       // 10240
#define STAGE_B  (4 * TILE_B)         // 40960: [Ah][Al][Bh][Bl]
#define GEMM_SMEM (2 * STAGE_B)       // 81920

#define LOAD_STAGE(stg, kc) do {                                            \
    const int _kb = (kc) * 32;                                              \
    _Pragma("unroll")                                                       \
    for (int _j = 0; _j < 8; _j++) {                                        \
        int _u = _j * 256 + tid;                                            \
        int _tile = _u >> 9, _v = _u & 511;                                 \
        int _row = _v >> 2, _cc = _v & 3;                                   \
        uint32_t _sa = sb + (stg) * STAGE_B + _tile * TILE_B                \
                     + _row * PITCHB + _cc * 16;                            \
        const __nv_bfloat16* _gp;                                           \
        if      (_tile == 0) _gp = Ah + (size_t)(bm + _row) * EE;           \
        else if (_tile == 1) _gp = Al + (size_t)(bm + _row) * EE;           \
        else if (_tile == 2) _gp = Bh + (size_t)(bn + _row) * EE;           \
        else                 _gp = Bl + (size_t)(bn + _row) * EE;           \
        cpasync16(_sa, _gp + _kb + _cc * 8);                                \
    }                                                                       \
    CP_COMMIT();                                                            \
} while (0)

__global__ __launch_bounds__(256) void gemm_mma(
    const __nv_bfloat16* __restrict__ Ah, const __nv_bfloat16* __restrict__ Al,
    const __nv_bfloat16* __restrict__ Bh, const __nv_bfloat16* __restrict__ Bl,
    const float* __restrict__ bias, float* __restrict__ Out)
{
    extern __shared__ char smem[];
    const uint32_t sb = smem_u32(smem);
    const int tid  = threadIdx.x;
    const int wid  = tid >> 5;
    const int lane = tid & 31;
    const int wm   = wid & 1;     // 0..1  (64 rows each)
    const int wn   = wid >> 1;    // 0..3  (32 cols each)
    const int bm   = blockIdx.y * 128;
    const int bn   = blockIdx.x * 128;

    float acc[4][4][4];
    #pragma unroll
    for (int i = 0; i < 4; i++)
        #pragma unroll
        for (int j = 0; j < 4; j++)
            #pragma unroll
            for (int q = 0; q < 4; q++) acc[i][j][q] = 0.0f;

    LOAD_STAGE(0, 0);

    const uint32_t lrow16 = (uint32_t)(lane & 15);
    const uint32_t lcol16 = (uint32_t)((lane >> 4) << 4);

    for (int kc = 0; kc < 16; kc++) {
        if (kc < 15) { LOAD_STAGE((kc + 1) & 1, kc + 1); CP_WAIT(1); }
        else         { CP_WAIT(0); }
        __syncthreads();

        const uint32_t stg = sb + (kc & 1) * STAGE_B;
        #pragma unroll
        for (int kk = 0; kk < 2; kk++) {
            uint32_t ah[4][4], al[4][4], bh[2][4], bl[2][4];
            #pragma unroll
            for (int tm = 0; tm < 4; tm++) {
                uint32_t row = wm * 64 + tm * 16 + lrow16;
                uint32_t ad  = stg + row * PITCHB + kk * 32 + lcol16;
                ldsm4(ah[tm], ad);
                ldsm4(al[tm], ad + TILE_B);
            }
            #pragma unroll
            for (int t2 = 0; t2 < 2; t2++) {
                uint32_t row = wn * 32 + t2 * 16 + lrow16;
                uint32_t bd  = stg + 2 * TILE_B + row * PITCHB + kk * 32 + lcol16;
                ldsm4(bh[t2], bd);
                ldsm4(bl[t2], bd + TILE_B);
            }
            #pragma unroll
            for (int tm = 0; tm < 4; tm++)
                #pragma unroll
                for (int tn = 0; tn < 4; tn++) {
                    const int t2 = tn >> 1, hi = tn & 1;
                    // x4 over [n16][k16]: r0=b0@n0-7, r1=b0@n8-15, r2=b1@n0-7, r3=b1@n8-15
                    mma16816(acc[tm][tn], ah[tm], bh[t2][hi], bh[t2][2 + hi]);
                    mma16816(acc[tm][tn], ah[tm], bl[t2][hi], bl[t2][2 + hi]);
                    mma16816(acc[tm][tn], al[tm], bh[t2][hi], bh[t2][2 + hi]);
                }
        }
        __syncthreads();
    }

    // Epilogue: c0,c1 -> (row, col..col+1); c2,c3 -> (row+8, ...)
    const int r0 = bm + wm * 64 + (lane >> 2);
    const int c0 = bn + wn * 32 + ((lane & 3) << 1);
    #pragma unroll
    for (int tm = 0; tm < 4; tm++) {
        #pragma unroll
        for (int tn = 0; tn < 4; tn++) {
            int row = r0 + tm * 16;
            int col = c0 + tn * 8;
            float bv0 = bias[col], bv1 = bias[col + 1];
            float2 o0 = make_float2(acc[tm][tn][0] + bv0, acc[tm][tn][1] + bv1);
            float2 o1 = make_float2(acc[tm][tn][2] + bv0, acc[tm][tn][3] + bv1);
            *reinterpret_cast<float2*>(Out + (size_t)row * EE + col)       = o0;
            *reinterpret_cast<float2*>(Out + (size_t)(row + 8) * EE + col) = o1;
        }
    }
}

// ---------------------------------------------------------------------------
// Sparse tree attention, 8-warp parallel scan (deterministic, ascending m).
// ---------------------------------------------------------------------------
__global__ __launch_bounds__(256) void tree_attn(const int* __restrict__ parent)
{
    const int bn = blockIdx.x;
    const int b  = bn >> 11;
    const int n  = bn & (SS - 1);

    __shared__ int list[8][256];
    __shared__ int cnts[8];

    const int t    = threadIdx.x;
    const int warp = t >> 5;
    const int lane = t & 31;

    const int par_n = parent[b * SS + n];

    int base = 0;
    const int m_lo = warp * 256;
    for (int m0 = m_lo; m0 < m_lo + 256; m0 += 32) {
        int m = m0 + lane;
        bool pred = (m == par_n) || (parent[b * SS + m] == n);
        unsigned bal = __ballot_sync(0xffffffffu, pred);
        int pos = __popc(bal & ((1u << lane) - 1u));
        if (pred) list[warp][base + pos] = m;
        base += __popc(bal);
    }
    if (lane == 0) cnts[warp] = base;
    __syncthreads();

    const float* Prow = &g_P[(size_t)bn * EE + warp * DD];
    const float p0 = Prow[lane];
    const float p1 = Prow[lane + 32];

    float m_run = -1e30f, l_run = 0.0f, a0 = 0.0f, a1 = 0.0f;
    const float scale = 0.125f;  // 1/sqrt(64)

    for (int w = 0; w < 8; w++) {
        const int cw = cnts[w];
        for (int i = 0; i < cw; i++) {
            int m = list[w][i];
            const size_t mrow = ((size_t)b * SS + m) * EE + warp * DD;
            const float* Crow = &g_C[mrow];
            float part = p0 * Crow[lane] + p1 * Crow[lane + 32];
            #pragma unroll
            for (int off = 16; off; off >>= 1)
                part += __shfl_xor_sync(0xffffffffu, part, off);
            float scr = part * scale;

            float m_new = fmaxf(m_run, scr);
            float corr  = __expf(m_run - m_new);
            float wgt   = __expf(scr - m_new);
            const float* Srow = &g_Sv[mrow];
            a0 = a0 * corr + wgt * Srow[lane];
            a1 = a1 * corr + wgt * Srow[lane + 32];
            l_run = l_run * corr + wgt;
            m_run = m_new;
        }
    }

    const float inv = 1.0f / l_run;
    float* Orow = &g_AO[(size_t)bn * EE + warp * DD];
    Orow[lane]      = a0 * inv;
    Orow[lane + 32] = a1 * inv;
}

// ---------------------------------------------------------------------------
extern "C" void kernel_launch(void* const* d_in, const int* in_sizes, int n_in,
                              void* d_out, int out_size)
{
    (void)in_sizes; (void)n_in; (void)out_size;
    const float* x      = (const float*)d_in[0];
    const int*   parent = (const int*)  d_in[1];
    const float* Wp = (const float*)d_in[2];
    const float* bp = (const float*)d_in[3];
    const float* Wc = (const float*)d_in[4];
    const float* bc = (const float*)d_in[5];
    const float* Ws = (const float*)d_in[6];
    const float* bs = (const float*)d_in[7];
    const float* Wo = (const float*)d_in[8];
    const float* bo = (const float*)d_in[9];
    float* out = (float*)d_out;

    float *P, *C, *Sv, *AO;
    __nv_bfloat16 *xh, *xl, *aoh, *aol, *Wth, *Wtl;
    cudaGetSymbolAddress((void**)&P,   g_P);
    cudaGetSymbolAddress((void**)&C,   g_C);
    cudaGetSymbolAddress((void**)&Sv,  g_Sv);
    cudaGetSymbolAddress((void**)&AO,  g_AO);
    cudaGetSymbolAddress((void**)&xh,  g_xh);
    cudaGetSymbolAddress((void**)&xl,  g_xl);
    cudaGetSymbolAddress((void**)&aoh, g_aoh);
    cudaGetSymbolAddress((void**)&aol, g_aol);
    cudaGetSymbolAddress((void**)&Wth, g_Wth);
    cudaGetSymbolAddress((void**)&Wtl, g_Wtl);

    static bool attr_done = false;
    if (!attr_done) {
        cudaFuncSetAttribute(gemm_mma,
            cudaFuncAttributeMaxDynamicSharedMemorySize, GEMM_SMEM);
        attr_done = true;
    }

    const int n4 = MT * EE / 4;
    split_f32<<<(n4 + 255) / 256, 256>>>(x, xh, xl, n4);

    dim3 wgrid(16, 16), wblk(32, 8);
    wsplit_t<<<wgrid, wblk>>>(Wp, Wth + 0 * EE * EE, Wtl + 0 * EE * EE);
    wsplit_t<<<wgrid, wblk>>>(Wc, Wth + 1 * EE * EE, Wtl + 1 * EE * EE);
    wsplit_t<<<wgrid, wblk>>>(Ws, Wth + 2 * EE * EE, Wtl + 2 * EE * EE);
    wsplit_t<<<wgrid, wblk>>>(Wo, Wth + 3 * EE * EE, Wtl + 3 * EE * EE);

    dim3 ggrid(EE / 128, MT / 128);   // (4, 32) = 128 CTAs
    gemm_mma<<<ggrid, 256, GEMM_SMEM>>>(xh, xl, Wth + 0*EE*EE, Wtl + 0*EE*EE, bp, P);
    gemm_mma<<<ggrid, 256, GEMM_SMEM>>>(xh, xl, Wth + 1*EE*EE, Wtl + 1*EE*EE, bc, C);
    gemm_mma<<<ggrid, 256, GEMM_SMEM>>>(xh, xl, Wth + 2*EE*EE, Wtl + 2*EE*EE, bs, Sv);

    tree_attn<<<MT, 256>>>(parent);

    split_f32<<<(n4 + 255) / 256, 256>>>(AO, aoh, aol, n4);
    gemm_mma<<<ggrid, 256, GEMM_SMEM>>>(aoh, aol, Wth + 3*EE*EE, Wtl + 3*EE*EE, bo, out);
}

// round 5
// speedup vs baseline: 3.1608x; 1.5305x over previous
#include <cuda_runtime.h>
#include <cuda_fp16.h>
#include <cstdint>

#define BB 2
#define SS 2048
#define EE 512
#define HH 8
#define DD 64
#define MT (BB*SS)     // 4096 rows
#define NPROJ 1536     // fused P|C|S output width

// ---------------------------------------------------------------------------
// Scratch (device globals: allocation-free per harness rules)
// ---------------------------------------------------------------------------
__device__ float  g_PCS[MT*NPROJ];                 // P|C|S fused, stride 1536
__device__ __align__(16) __half g_xh [MT*EE];
__device__ __align__(16) __half g_xl [MT*EE];
__device__ __align__(16) __half g_aoh[MT*EE];
__device__ __align__(16) __half g_aol[MT*EE];
__device__ __align__(16) __half g_Wt [4][EE*EE];   // transposed [N][K], fp16
__device__ float  g_bcat[NPROJ];                   // bp|bc|bs

// ---------------------------------------------------------------------------
// Helpers (base-target PTX only: ldmatrix / mma.sync / cp.async)
// ---------------------------------------------------------------------------
__device__ __forceinline__ uint32_t smem_u32(const void* p) {
    uint32_t a;
    asm("{ .reg .u64 t; cvta.to.shared.u64 t, %1; cvt.u32.u64 %0, t; }"
        : "=r"(a) : "l"(p));
    return a;
}
__device__ __forceinline__ void ldsm4(uint32_t* r, uint32_t addr) {
    asm volatile("ldmatrix.sync.aligned.m8n8.x4.shared.b16 {%0,%1,%2,%3}, [%4];"
        : "=r"(r[0]), "=r"(r[1]), "=r"(r[2]), "=r"(r[3]) : "r"(addr));
}
__device__ __forceinline__ void mma16816(float* d, const uint32_t* a,
                                         uint32_t b0, uint32_t b1) {
    asm volatile("mma.sync.aligned.m16n8k16.row.col.f32.f16.f16.f32 "
        "{%0,%1,%2,%3}, {%4,%5,%6,%7}, {%8,%9}, {%0,%1,%2,%3};"
        : "+f"(d[0]), "+f"(d[1]), "+f"(d[2]), "+f"(d[3])
        : "r"(a[0]), "r"(a[1]), "r"(a[2]), "r"(a[3]), "r"(b0), "r"(b1));
}
__device__ __forceinline__ void cpasync16(uint32_t saddr, const void* g) {
    asm volatile("cp.async.cg.shared.global [%0], [%1], 16;"
                 :: "r"(saddr), "l"(g) : "memory");
}
#define CP_COMMIT() asm volatile("cp.async.commit_group;" ::: "memory")
#define CP_WAIT(n)  asm volatile("cp.async.wait_group %0;" :: "n"(n) : "memory")

// ---------------------------------------------------------------------------
// Split fp32 x -> (hi, lo) fp16. n4 = elems/4.
// ---------------------------------------------------------------------------
__global__ __launch_bounds__(256) void split_x(
    const float* __restrict__ in, __half* __restrict__ hi,
    __half* __restrict__ lo, int n4)
{
    int i = blockIdx.x * 256 + threadIdx.x;
    if (i >= n4) return;
    float4 v = reinterpret_cast<const float4*>(in)[i];
    __half h0 = __float2half_rn(v.x);
    __half h1 = __float2half_rn(v.y);
    __half h2 = __float2half_rn(v.z);
    __half h3 = __float2half_rn(v.w);
    __half l0 = __float2half_rn(v.x - __half2float(h0));
    __half l1 = __float2half_rn(v.y - __half2float(h1));
    __half l2 = __float2half_rn(v.z - __half2float(h2));
    __half l3 = __float2half_rn(v.w - __half2float(h3));
    reinterpret_cast<__half2*>(hi)[i*2+0] = __halves2half2(h0, h1);
    reinterpret_cast<__half2*>(hi)[i*2+1] = __halves2half2(h2, h3);
    reinterpret_cast<__half2*>(lo)[i*2+0] = __halves2half2(l0, l1);
    reinterpret_cast<__half2*>(lo)[i*2+1] = __halves2half2(l2, l3);
}

// ---------------------------------------------------------------------------
// All 4 weights: transpose 512x512 -> fp16 [N][K]; plus bias concat.
// grid 1024 (w = bid>>8, tile = bid&255), block (32,8)
// ---------------------------------------------------------------------------
__global__ __launch_bounds__(256) void wsplit_all(
    const float* __restrict__ Wp, const float* __restrict__ Wc,
    const float* __restrict__ Ws, const float* __restrict__ Wo,
    const float* __restrict__ bp, const float* __restrict__ bc,
    const float* __restrict__ bs,
    __half* __restrict__ Wt, float* __restrict__ bcat)
{
    __shared__ float t[32][33];
    const int bid  = blockIdx.x;
    const int w    = bid >> 8;
    const int tile = bid & 255;
    const int k0 = (tile & 15) * 32, n0 = (tile >> 4) * 32;
    const float* W = (w == 0) ? Wp : (w == 1) ? Wc : (w == 2) ? Ws : Wo;
    __half* out = Wt + (size_t)w * EE * EE;
    const int tx = threadIdx.x;

    for (int j = threadIdx.y; j < 32; j += 8)
        t[j][tx] = W[(size_t)(k0 + j) * EE + n0 + tx];
    __syncthreads();
    for (int j = threadIdx.y; j < 32; j += 8)
        out[(size_t)(n0 + j) * EE + k0 + tx] = __float2half_rn(t[tx][j]);

    if (bid < 6) {
        int i = bid * 256 + threadIdx.y * 32 + tx;
        float v = (i < 512) ? bp[i] : (i < 1024) ? bc[i - 512] : bs[i - 1024];
        bcat[i] = v;
    }
}

// ---------------------------------------------------------------------------
// mma.sync 2-term fp16 GEMM: Out[M,Nst] = (Ah+Al)[M,512] @ Wh^T + bias
// A as (Ah, Al) fp16 K-major; B = Wt[N][K] fp16.
// CTA 128x128, 8 warps (2 M x 4 N), warp tile 64x32, K-chunk 32, 2 stages.
// smem: 3 tiles x 128 rows x 80B pitch, double-buffered.
// ---------------------------------------------------------------------------
#define PITCHB   80
#define TILE_B   (128 * PITCHB)       // 10240
#define STAGE_B  (3 * TILE_B)         // 30720: [Ah][Al][Bh]
#define GEMM_SMEM (2 * STAGE_B)       // 61440

#define LOAD_STAGE(stg, kc) do {                                            \
    const int _kb = (kc) * 32;                                              \
    _Pragma("unroll")                                                       \
    for (int _j = 0; _j < 6; _j++) {                                        \
        int _u = _j * 256 + tid;                                            \
        int _tile = _u >> 9, _v = _u & 511;                                 \
        int _row = _v >> 2, _cc = _v & 3;                                   \
        uint32_t _sa = sb + (stg) * STAGE_B + _tile * TILE_B                \
                     + _row * PITCHB + _cc * 16;                            \
        const __half* _gp;                                                  \
        if      (_tile == 0) _gp = Ah + (size_t)(bm + _row) * EE;           \
        else if (_tile == 1) _gp = Al + (size_t)(bm + _row) * EE;           \
        else                 _gp = Bh + (size_t)(bn + _row) * EE;           \
        cpasync16(_sa, _gp + _kb + _cc * 8);                                \
    }                                                                       \
    CP_COMMIT();                                                            \
} while (0)

__global__ __launch_bounds__(256) void gemm_mma(
    const __half* __restrict__ Ah, const __half* __restrict__ Al,
    const __half* __restrict__ Bh,
    const float* __restrict__ bias, float* __restrict__ Out, int Nst)
{
    extern __shared__ char smem[];
    const uint32_t sb = smem_u32(smem);
    const int tid  = threadIdx.x;
    const int wid  = tid >> 5;
    const int lane = tid & 31;
    const int wm   = wid & 1;     // 0..1  (64 rows)
    const int wn   = wid >> 1;    // 0..3  (32 cols)
    const int bm   = blockIdx.y * 128;
    const int bn   = blockIdx.x * 128;

    float acc[4][4][4];
    #pragma unroll
    for (int i = 0; i < 4; i++)
        #pragma unroll
        for (int j = 0; j < 4; j++)
            #pragma unroll
            for (int q = 0; q < 4; q++) acc[i][j][q] = 0.0f;

    LOAD_STAGE(0, 0);

    const uint32_t lrow16 = (uint32_t)(lane & 15);
    const uint32_t lcol16 = (uint32_t)((lane >> 4) << 4);

    for (int kc = 0; kc < 16; kc++) {
        if (kc < 15) { LOAD_STAGE((kc + 1) & 1, kc + 1); CP_WAIT(1); }
        else         { CP_WAIT(0); }
        __syncthreads();

        const uint32_t stg = sb + (kc & 1) * STAGE_B;
        #pragma unroll
        for (int kk = 0; kk < 2; kk++) {
            uint32_t ah[4][4], al[4][4], bh[2][4];
            #pragma unroll
            for (int tm = 0; tm < 4; tm++) {
                uint32_t row = wm * 64 + tm * 16 + lrow16;
                uint32_t ad  = stg + row * PITCHB + kk * 32 + lcol16;
                ldsm4(ah[tm], ad);
                ldsm4(al[tm], ad + TILE_B);
            }
            #pragma unroll
            for (int t2 = 0; t2 < 2; t2++) {
                uint32_t row = wn * 32 + t2 * 16 + lrow16;
                uint32_t bd  = stg + 2 * TILE_B + row * PITCHB + kk * 32 + lcol16;
                ldsm4(bh[t2], bd);
            }
            #pragma unroll
            for (int tm = 0; tm < 4; tm++)
                #pragma unroll
                for (int tn = 0; tn < 4; tn++) {
                    const int t2 = tn >> 1, hi = tn & 1;
                    mma16816(acc[tm][tn], ah[tm], bh[t2][hi], bh[t2][2 + hi]);
                    mma16816(acc[tm][tn], al[tm], bh[t2][hi], bh[t2][2 + hi]);
                }
        }
        __syncthreads();
    }

    const int r0 = bm + wm * 64 + (lane >> 2);
    const int c0 = bn + wn * 32 + ((lane & 3) << 1);
    #pragma unroll
    for (int tm = 0; tm < 4; tm++) {
        #pragma unroll
        for (int tn = 0; tn < 4; tn++) {
            int row = r0 + tm * 16;
            int col = c0 + tn * 8;
            float bv0 = bias[col], bv1 = bias[col + 1];
            float2 o0 = make_float2(acc[tm][tn][0] + bv0, acc[tm][tn][1] + bv1);
            float2 o1 = make_float2(acc[tm][tn][2] + bv0, acc[tm][tn][3] + bv1);
            *reinterpret_cast<float2*>(Out + (size_t)row * Nst + col)       = o0;
            *reinterpret_cast<float2*>(Out + (size_t)(row + 8) * Nst + col) = o1;
        }
    }
}

// ---------------------------------------------------------------------------
// Sparse tree attention over fused PCS buffer; writes fp16 hi/lo directly.
// One block per (b, n); 8-warp deterministic neighbor scan (ascending m).
// ---------------------------------------------------------------------------
__global__ __launch_bounds__(256) void tree_attn(const int* __restrict__ parent,
                                                 __half* __restrict__ aoh,
                                                 __half* __restrict__ aol)
{
    const int bn = blockIdx.x;
    const int b  = bn >> 11;
    const int n  = bn & (SS - 1);

    __shared__ int list[8][256];
    __shared__ int cnts[8];

    const int t    = threadIdx.x;
    const int warp = t >> 5;
    const int lane = t & 31;

    const int par_n = parent[b * SS + n];

    int base = 0;
    const int m_lo = warp * 256;
    for (int m0 = m_lo; m0 < m_lo + 256; m0 += 32) {
        int m = m0 + lane;
        bool pred = (m == par_n) || (parent[b * SS + m] == n);
        unsigned bal = __ballot_sync(0xffffffffu, pred);
        int pos = __popc(bal & ((1u << lane) - 1u));
        if (pred) list[warp][base + pos] = m;
        base += __popc(bal);
    }
    if (lane == 0) cnts[warp] = base;
    __syncthreads();

    // PCS row layout: [P(512) | C(512) | S(512)]
    const float* Prow = &g_PCS[(size_t)bn * NPROJ + warp * DD];
    const float p0 = Prow[lane];
    const float p1 = Prow[lane + 32];

    float m_run = -1e30f, l_run = 0.0f, a0 = 0.0f, a1 = 0.0f;
    const float scale = 0.125f;  // 1/sqrt(64)

    for (int w = 0; w < 8; w++) {
        const int cw = cnts[w];
        for (int i = 0; i < cw; i++) {
            int m = list[w][i];
            const float* mbase = &g_PCS[((size_t)b * SS + m) * NPROJ + warp * DD];
            const float* Crow = mbase + 512;
            float part = p0 * Crow[lane] + p1 * Crow[lane + 32];
            #pragma unroll
            for (int off = 16; off; off >>= 1)
                part += __shfl_xor_sync(0xffffffffu, part, off);
            float scr = part * scale;

            float m_new = fmaxf(m_run, scr);
            float corr  = __expf(m_run - m_new);
            float wgt   = __expf(scr - m_new);
            const float* Srow = mbase + 1024;
            a0 = a0 * corr + wgt * Srow[lane];
            a1 = a1 * corr + wgt * Srow[lane + 32];
            l_run = l_run * corr + wgt;
            m_run = m_new;
        }
    }

    const float inv = 1.0f / l_run;
    const float v0 = a0 * inv, v1 = a1 * inv;
    __half h0 = __float2half_rn(v0), h1 = __float2half_rn(v1);
    __half l0 = __float2half_rn(v0 - __half2float(h0));
    __half l1 = __float2half_rn(v1 - __half2float(h1));
    const size_t obase = (size_t)bn * EE + warp * DD;
    aoh[obase + lane]      = h0;
    aoh[obase + lane + 32] = h1;
    aol[obase + lane]      = l0;
    aol[obase + lane + 32] = l1;
}

// ---------------------------------------------------------------------------
extern "C" void kernel_launch(void* const* d_in, const int* in_sizes, int n_in,
                              void* d_out, int out_size)
{
    (void)in_sizes; (void)n_in; (void)out_size;
    const float* x      = (const float*)d_in[0];
    const int*   parent = (const int*)  d_in[1];
    const float* Wp = (const float*)d_in[2];
    const float* bp = (const float*)d_in[3];
    const float* Wc = (const float*)d_in[4];
    const float* bc = (const float*)d_in[5];
    const float* Ws = (const float*)d_in[6];
    const float* bs = (const float*)d_in[7];
    const float* Wo = (const float*)d_in[8];
    const float* bo = (const float*)d_in[9];
    float* out = (float*)d_out;

    float *PCS, *bcat;
    __half *xh, *xl, *aoh, *aol, *Wt;
    cudaGetSymbolAddress((void**)&PCS,  g_PCS);
    cudaGetSymbolAddress((void**)&bcat, g_bcat);
    cudaGetSymbolAddress((void**)&xh,   g_xh);
    cudaGetSymbolAddress((void**)&xl,   g_xl);
    cudaGetSymbolAddress((void**)&aoh,  g_aoh);
    cudaGetSymbolAddress((void**)&aol,  g_aol);
    cudaGetSymbolAddress((void**)&Wt,   g_Wt);

    static bool attr_done = false;
    if (!attr_done) {
        cudaFuncSetAttribute(gemm_mma,
            cudaFuncAttributeMaxDynamicSharedMemorySize, GEMM_SMEM);
        attr_done = true;
    }

    const int n4 = MT * EE / 4;
    split_x<<<(n4 + 255) / 256, 256>>>(x, xh, xl, n4);
    wsplit_all<<<1024, dim3(32, 8)>>>(Wp, Wc, Ws, Wo, bp, bc, bs, Wt, bcat);

    // Fused projection GEMM: N = 1536 (Wp|Wc|Ws transposed are contiguous)
    dim3 pgrid(NPROJ / 128, MT / 128);   // (12, 32)
    gemm_mma<<<pgrid, 256, GEMM_SMEM>>>(xh, xl, Wt, bcat, PCS, NPROJ);

    tree_attn<<<MT, 256>>>(parent, aoh, aol);

    dim3 ogrid(EE / 128, MT / 128);      // (4, 32)
    gemm_mma<<<ogrid, 256, GEMM_SMEM>>>(aoh, aol, Wt + 3 * EE * EE, bo, out, EE);
}

// round 7
// speedup vs baseline: 4.7635x; 1.5070x over previous
#include <cuda_runtime.h>
#include <cuda_fp16.h>
#include <cstdint>

#define BB 2
#define SS 2048
#define EE 512
#define HH 8
#define DD 64
#define MT (BB*SS)     // 4096 rows
#define NPROJ 1536     // fused P|C|S output width

// ---------------------------------------------------------------------------
// Scratch (device globals: allocation-free per harness rules)
// ---------------------------------------------------------------------------
__device__ float  g_PCS[MT*NPROJ];                 // P|C|S fused, stride 1536
__device__ __align__(16) __half g_xh [MT*EE];
__device__ __align__(16) __half g_aoh[MT*EE];
__device__ __align__(16) __half g_Wt [4][EE*EE];   // transposed [N][K], fp16
__device__ float  g_bcat[NPROJ];                   // bp|bc|bs

// ---------------------------------------------------------------------------
// Helpers (base-target PTX only: ldmatrix / mma.sync / cp.async)
// ---------------------------------------------------------------------------
__device__ __forceinline__ uint32_t smem_u32(const void* p) {
    uint32_t a;
    asm("{ .reg .u64 t; cvta.to.shared.u64 t, %1; cvt.u32.u64 %0, t; }"
        : "=r"(a) : "l"(p));
    return a;
}
__device__ __forceinline__ void ldsm4(uint32_t* r, uint32_t addr) {
    asm volatile("ldmatrix.sync.aligned.m8n8.x4.shared.b16 {%0,%1,%2,%3}, [%4];"
        : "=r"(r[0]), "=r"(r[1]), "=r"(r[2]), "=r"(r[3]) : "r"(addr));
}
__device__ __forceinline__ void mma16816(float* d, const uint32_t* a,
                                         uint32_t b0, uint32_t b1) {
    asm volatile("mma.sync.aligned.m16n8k16.row.col.f32.f16.f16.f32 "
        "{%0,%1,%2,%3}, {%4,%5,%6,%7}, {%8,%9}, {%0,%1,%2,%3};"
        : "+f"(d[0]), "+f"(d[1]), "+f"(d[2]), "+f"(d[3])
        : "r"(a[0]), "r"(a[1]), "r"(a[2]), "r"(a[3]), "r"(b0), "r"(b1));
}
__device__ __forceinline__ void cpasync16(uint32_t saddr, const void* g) {
    asm volatile("cp.async.cg.shared.global [%0], [%1], 16;"
                 :: "r"(saddr), "l"(g) : "memory");
}
#define CP_COMMIT() asm volatile("cp.async.commit_group;" ::: "memory")
#define CP_WAIT(n)  asm volatile("cp.async.wait_group %0;" :: "n"(n) : "memory")

// ---------------------------------------------------------------------------
// Combined prep: blocks [0,1024) transpose the 4 weights to fp16 [N][K];
// blocks [1024,2048) convert x to fp16; first 6 blocks also concat biases.
// ---------------------------------------------------------------------------
__global__ __launch_bounds__(256) void prep_all(
    const float* __restrict__ Wp, const float* __restrict__ Wc,
    const float* __restrict__ Ws, const float* __restrict__ Wo,
    const float* __restrict__ bp, const float* __restrict__ bc,
    const float* __restrict__ bs, const float* __restrict__ x,
    __half* __restrict__ Wt, float* __restrict__ bcat,
    __half* __restrict__ xh)
{
    const int bid = blockIdx.x;
    if (bid < 1024) {
        __shared__ float t[32][33];
        const int w    = bid >> 8;
        const int tile = bid & 255;
        const int k0 = (tile & 15) * 32, n0 = (tile >> 4) * 32;
        const float* W = (w == 0) ? Wp : (w == 1) ? Wc : (w == 2) ? Ws : Wo;
        __half* out = Wt + (size_t)w * EE * EE;
        const int tx = threadIdx.x & 31;
        const int ty = threadIdx.x >> 5;

        for (int j = ty; j < 32; j += 8)
            t[j][tx] = W[(size_t)(k0 + j) * EE + n0 + tx];
        __syncthreads();
        for (int j = ty; j < 32; j += 8)
            out[(size_t)(n0 + j) * EE + k0 + tx] = __float2half_rn(t[tx][j]);

        if (bid < 6) {
            int i = bid * 256 + threadIdx.x;
            bcat[i] = (i < 512) ? bp[i] : (i < 1024) ? bc[i - 512] : bs[i - 1024];
        }
    } else {
        // x convert: 2 float4 per thread -> 1024 blocks cover MT*EE elems
        const int base = (bid - 1024) * 512 + threadIdx.x;
        #pragma unroll
        for (int r = 0; r < 2; r++) {
            int i = base + r * 256;          // float4 index
            float4 v = reinterpret_cast<const float4*>(x)[i];
            __half2 h01 = __halves2half2(__float2half_rn(v.x), __float2half_rn(v.y));
            __half2 h23 = __halves2half2(__float2half_rn(v.z), __float2half_rn(v.w));
            reinterpret_cast<__half2*>(xh)[i*2+0] = h01;
            reinterpret_cast<__half2*>(xh)[i*2+1] = h23;
        }
    }
}

// ---------------------------------------------------------------------------
// mma.sync fp16 GEMM: Out[M,Nst] = A[M,512] @ Wt^T + bias
// A fp16 K-major [M][512]; B = Wt[N][K] fp16.
// CTA 128x128, 8 warps (2 M x 4 N), warp tile 64x32, K-chunk 32, 3 stages.
// smem: 2 tiles x 128 rows x 80B pitch per stage, triple-buffered.
// ---------------------------------------------------------------------------
#define PITCHB   80
#define TILE_B   (128 * PITCHB)       // 10240
#define STAGE_B  (2 * TILE_B)         // 20480: [A][B]
#define GEMM_SMEM (3 * STAGE_B)       // 61440

#define LOAD_STAGE(stg, kc) do {                                            \
    const int _kb = (kc) * 32;                                              \
    _Pragma("unroll")                                                       \
    for (int _j = 0; _j < 4; _j++) {                                        \
        int _u = _j * 256 + tid;                                            \
        int _tile = _u >> 9, _v = _u & 511;                                 \
        int _row = _v >> 2, _cc = _v & 3;                                   \
        uint32_t _sa = sb + (stg) * STAGE_B + _tile * TILE_B                \
                     + _row * PITCHB + _cc * 16;                            \
        const __half* _gp = (_tile == 0)                                    \
            ? Ah + (size_t)(bm + _row) * EE                                 \
            : Bh + (size_t)(bn + _row) * EE;                                \
        cpasync16(_sa, _gp + _kb + _cc * 8);                                \
    }                                                                       \
    CP_COMMIT();                                                            \
} while (0)

__global__ __launch_bounds__(256) void gemm_mma(
    const __half* __restrict__ Ah, const __half* __restrict__ Bh,
    const float* __restrict__ bias, float* __restrict__ Out, int Nst)
{
    extern __shared__ char smem[];
    const uint32_t sb = smem_u32(smem);
    const int tid  = threadIdx.x;
    const int wid  = tid >> 5;
    const int lane = tid & 31;
    const int wm   = wid & 1;     // 0..1  (64 rows)
    const int wn   = wid >> 1;    // 0..3  (32 cols)
    const int bm   = blockIdx.y * 128;
    const int bn   = blockIdx.x * 128;

    float acc[4][4][4];
    #pragma unroll
    for (int i = 0; i < 4; i++)
        #pragma unroll
        for (int j = 0; j < 4; j++)
            #pragma unroll
            for (int q = 0; q < 4; q++) acc[i][j][q] = 0.0f;

    LOAD_STAGE(0, 0);
    LOAD_STAGE(1, 1);

    const uint32_t lrow16 = (uint32_t)(lane & 15);
    const uint32_t lcol16 = (uint32_t)((lane >> 4) << 4);

    int stage = 0;
    for (int kc = 0; kc < 16; kc++) {
        if (kc < 14)      { LOAD_STAGE((stage + 2) % 3, kc + 2); CP_WAIT(2); }
        else if (kc == 14){ CP_WAIT(1); }
        else              { CP_WAIT(0); }
        __syncthreads();

        const uint32_t stg = sb + stage * STAGE_B;
        #pragma unroll
        for (int kk = 0; kk < 2; kk++) {
            uint32_t ah[4][4], bh[2][4];
            #pragma unroll
            for (int tm = 0; tm < 4; tm++) {
                uint32_t row = wm * 64 + tm * 16 + lrow16;
                ldsm4(ah[tm], stg + row * PITCHB + kk * 32 + lcol16);
            }
            #pragma unroll
            for (int t2 = 0; t2 < 2; t2++) {
                uint32_t row = wn * 32 + t2 * 16 + lrow16;
                ldsm4(bh[t2], stg + TILE_B + row * PITCHB + kk * 32 + lcol16);
            }
            #pragma unroll
            for (int tm = 0; tm < 4; tm++)
                #pragma unroll
                for (int tn = 0; tn < 4; tn++) {
                    const int t2 = tn >> 1, hi = tn & 1;
                    mma16816(acc[tm][tn], ah[tm], bh[t2][hi], bh[t2][2 + hi]);
                }
        }
        __syncthreads();
        stage = (stage + 1) % 3;
    }

    const int r0 = bm + wm * 64 + (lane >> 2);
    const int c0 = bn + wn * 32 + ((lane & 3) << 1);
    #pragma unroll
    for (int tm = 0; tm < 4; tm++) {
        #pragma unroll
        for (int tn = 0; tn < 4; tn++) {
            int row = r0 + tm * 16;
            int col = c0 + tn * 8;
            float bv0 = bias[col], bv1 = bias[col + 1];
            float2 o0 = make_float2(acc[tm][tn][0] + bv0, acc[tm][tn][1] + bv1);
            float2 o1 = make_float2(acc[tm][tn][2] + bv0, acc[tm][tn][3] + bv1);
            *reinterpret_cast<float2*>(Out + (size_t)row * Nst + col)       = o0;
            *reinterpret_cast<float2*>(Out + (size_t)(row + 8) * Nst + col) = o1;
        }
    }
}

// ---------------------------------------------------------------------------
// Sparse tree attention over fused PCS buffer; writes fp16 AO directly.
// One block per (b, n); 8-warp deterministic neighbor scan (ascending m).
// ---------------------------------------------------------------------------
__global__ __launch_bounds__(256) void tree_attn(const int* __restrict__ parent,
                                                 __half* __restrict__ aoh)
{
    const int bn = blockIdx.x;
    const int b  = bn >> 11;
    const int n  = bn & (SS - 1);

    __shared__ int list[8][256];
    __shared__ int cnts[8];

    const int t    = threadIdx.x;
    const int warp = t >> 5;
    const int lane = t & 31;

    const int par_n = parent[b * SS + n];

    int base = 0;
    const int m_lo = warp * 256;
    for (int m0 = m_lo; m0 < m_lo + 256; m0 += 32) {
        int m = m0 + lane;
        bool pred = (m == par_n) || (parent[b * SS + m] == n);
        unsigned bal = __ballot_sync(0xffffffffu, pred);
        int pos = __popc(bal & ((1u << lane) - 1u));
        if (pred) list[warp][base + pos] = m;
        base += __popc(bal);
    }
    if (lane == 0) cnts[warp] = base;
    __syncthreads();

    // PCS row layout: [P(512) | C(512) | S(512)]
    const float* Prow = &g_PCS[(size_t)bn * NPROJ + warp * DD];
    const float p0 = Prow[lane];
    const float p1 = Prow[lane + 32];

    float m_run = -1e30f, l_run = 0.0f, a0 = 0.0f, a1 = 0.0f;
    const float scale = 0.125f;  // 1/sqrt(64)

    for (int w = 0; w < 8; w++) {
        const int cw = cnts[w];
        for (int i = 0; i < cw; i++) {
            int m = list[w][i];
            const float* mbase = &g_PCS[((size_t)b * SS + m) * NPROJ + warp * DD];
            const float* Crow = mbase + 512;
            float part = p0 * Crow[lane] + p1 * Crow[lane + 32];
            #pragma unroll
            for (int off = 16; off; off >>= 1)
                part += __shfl_xor_sync(0xffffffffu, part, off);
            float scr = part * scale;

            float m_new = fmaxf(m_run, scr);
            float corr  = __expf(m_run - m_new);
            float wgt   = __expf(scr - m_new);
            const float* Srow = mbase + 1024;
            a0 = a0 * corr + wgt * Srow[lane];
            a1 = a1 * corr + wgt * Srow[lane + 32];
            l_run = l_run * corr + wgt;
            m_run = m_new;
        }
    }

    const float inv = 1.0f / l_run;
    const size_t obase = (size_t)bn * EE + warp * DD;
    aoh[obase + lane]      = __float2half_rn(a0 * inv);
    aoh[obase + lane + 32] = __float2half_rn(a1 * inv);
}

// ---------------------------------------------------------------------------
extern "C" void kernel_launch(void* const* d_in, const int* in_sizes, int n_in,
                              void* d_out, int out_size)
{
    (void)in_sizes; (void)n_in; (void)out_size;
    const float* x      = (const float*)d_in[0];
    const int*   parent = (const int*)  d_in[1];
    const float* Wp = (const float*)d_in[2];
    const float* bp = (const float*)d_in[3];
    const float* Wc = (const float*)d_in[4];
    const float* bc = (const float*)d_in[5];
    const float* Ws = (const float*)d_in[6];
    const float* bs = (const float*)d_in[7];
    const float* Wo = (const float*)d_in[8];
    const float* bo = (const float*)d_in[9];
    float* out = (float*)d_out;

    float *PCS, *bcat;
    __half *xh, *aoh, *Wt;
    cudaGetSymbolAddress((void**)&PCS,  g_PCS);
    cudaGetSymbolAddress((void**)&bcat, g_bcat);
    cudaGetSymbolAddress((void**)&xh,   g_xh);
    cudaGetSymbolAddress((void**)&aoh,  g_aoh);
    cudaGetSymbolAddress((void**)&Wt,   g_Wt);

    static bool attr_done = false;
    if (!attr_done) {
        cudaFuncSetAttribute(gemm_mma,
            cudaFuncAttributeMaxDynamicSharedMemorySize, GEMM_SMEM);
        attr_done = true;
    }

    prep_all<<<2048, 256>>>(Wp, Wc, Ws, Wo, bp, bc, bs, x, Wt, bcat, xh);

    // Fused projection GEMM: N = 1536 (Wp|Wc|Ws transposed are contiguous)
    dim3 pgrid(NPROJ / 128, MT / 128);   // (12, 32)
    gemm_mma<<<pgrid, 256, GEMM_SMEM>>>(xh, Wt, bcat, PCS, NPROJ);

    tree_attn<<<MT, 256>>>(parent, aoh);

    dim3 ogrid(EE / 128, MT / 128);      // (4, 32)
    gemm_mma<<<ogrid, 256, GEMM_SMEM>>>(aoh, Wt + 3 * EE * EE, bo, out, EE);
}

// round 8
// speedup vs baseline: 5.2393x; 1.0999x over previous
#include <cuda_runtime.h>
#include <cuda_fp16.h>
#include <cstdint>

#define BB 2
#define SS 2048
#define EE 512
#define HH 8
#define DD 64
#define MT (BB*SS)     // 4096 rows
#define NPROJ 1536     // fused P|C|S output width

// ---------------------------------------------------------------------------
// Scratch (device globals: allocation-free per harness rules)
// ---------------------------------------------------------------------------
__device__ float  g_PCS[MT*NPROJ];                 // P|C|S fused, stride 1536
__device__ __align__(16) __half g_xh [MT*EE];
__device__ __align__(16) __half g_aoh[MT*EE];
__device__ __align__(16) __half g_Wt [4][EE*EE];   // transposed [N][K], fp16
__device__ float  g_bcat[NPROJ];                   // bp|bc|bs

// ---------------------------------------------------------------------------
// Helpers (base-target PTX only: ldmatrix / mma.sync / cp.async)
// ---------------------------------------------------------------------------
__device__ __forceinline__ uint32_t smem_u32(const void* p) {
    uint32_t a;
    asm("{ .reg .u64 t; cvta.to.shared.u64 t, %1; cvt.u32.u64 %0, t; }"
        : "=r"(a) : "l"(p));
    return a;
}
__device__ __forceinline__ void ldsm4(uint32_t* r, uint32_t addr) {
    asm volatile("ldmatrix.sync.aligned.m8n8.x4.shared.b16 {%0,%1,%2,%3}, [%4];"
        : "=r"(r[0]), "=r"(r[1]), "=r"(r[2]), "=r"(r[3]) : "r"(addr));
}
__device__ __forceinline__ void mma16816(float* d, const uint32_t* a,
                                         uint32_t b0, uint32_t b1) {
    asm volatile("mma.sync.aligned.m16n8k16.row.col.f32.f16.f16.f32 "
        "{%0,%1,%2,%3}, {%4,%5,%6,%7}, {%8,%9}, {%0,%1,%2,%3};"
        : "+f"(d[0]), "+f"(d[1]), "+f"(d[2]), "+f"(d[3])
        : "r"(a[0]), "r"(a[1]), "r"(a[2]), "r"(a[3]), "r"(b0), "r"(b1));
}
__device__ __forceinline__ void cpasync16(uint32_t saddr, const void* g) {
    asm volatile("cp.async.cg.shared.global [%0], [%1], 16;"
                 :: "r"(saddr), "l"(g) : "memory");
}
#define CP_COMMIT() asm volatile("cp.async.commit_group;" ::: "memory")
#define CP_WAIT(n)  asm volatile("cp.async.wait_group %0;" :: "n"(n) : "memory")

// ---------------------------------------------------------------------------
// Combined prep: blocks [0,1024) transpose the 4 weights to fp16 [N][K];
// blocks [1024,2048) convert x to fp16; first 6 blocks also concat biases.
// ---------------------------------------------------------------------------
__global__ __launch_bounds__(256) void prep_all(
    const float* __restrict__ Wp, const float* __restrict__ Wc,
    const float* __restrict__ Ws, const float* __restrict__ Wo,
    const float* __restrict__ bp, const float* __restrict__ bc,
    const float* __restrict__ bs, const float* __restrict__ x,
    __half* __restrict__ Wt, float* __restrict__ bcat,
    __half* __restrict__ xh)
{
    const int bid = blockIdx.x;
    if (bid < 1024) {
        __shared__ float t[32][33];
        const int w    = bid >> 8;
        const int tile = bid & 255;
        const int k0 = (tile & 15) * 32, n0 = (tile >> 4) * 32;
        const float* W = (w == 0) ? Wp : (w == 1) ? Wc : (w == 2) ? Ws : Wo;
        __half* out = Wt + (size_t)w * EE * EE;
        const int tx = threadIdx.x & 31;
        const int ty = threadIdx.x >> 5;

        for (int j = ty; j < 32; j += 8)
            t[j][tx] = W[(size_t)(k0 + j) * EE + n0 + tx];
        __syncthreads();
        for (int j = ty; j < 32; j += 8)
            out[(size_t)(n0 + j) * EE + k0 + tx] = __float2half_rn(t[tx][j]);

        if (bid < 6) {
            int i = bid * 256 + threadIdx.x;
            bcat[i] = (i < 512) ? bp[i] : (i < 1024) ? bc[i - 512] : bs[i - 1024];
        }
    } else {
        const int base = (bid - 1024) * 512 + threadIdx.x;
        #pragma unroll
        for (int r = 0; r < 2; r++) {
            int i = base + r * 256;
            float4 v = reinterpret_cast<const float4*>(x)[i];
            __half2 h01 = __halves2half2(__float2half_rn(v.x), __float2half_rn(v.y));
            __half2 h23 = __halves2half2(__float2half_rn(v.z), __float2half_rn(v.w));
            reinterpret_cast<__half2*>(xh)[i*2+0] = h01;
            reinterpret_cast<__half2*>(xh)[i*2+1] = h23;
        }
    }
}

// ---------------------------------------------------------------------------
// mma.sync fp16 GEMM: Out[M,Nst] = A[M,512] @ Wt^T + bias
// Template TM: warp M-tiles of 16 rows; CTA tile = (32*TM) x 128.
// 8 warps (2 M x 4 N). K-chunk 64 (8 chunks), pitch 144 B (conflict-free:
// row stride 9*16B -> 9r mod 8 = r). 3-stage cp.async pipeline.
// Register-double-buffered ldmatrix: prefetch kk+1 frags during kk's MMAs.
// ---------------------------------------------------------------------------
#define GPITCH 144

template<int TM>
__global__ __launch_bounds__(256) void gemm_mma(
    const __half* __restrict__ Ah, const __half* __restrict__ Bh,
    const float* __restrict__ bias, float* __restrict__ Out, int Nst)
{
    constexpr int CTA_M  = 32 * TM;
    constexpr int TILE_A = CTA_M * GPITCH;
    constexpr int ROWS   = CTA_M + 128;
    constexpr int STAGE  = ROWS * GPITCH;
    constexpr int ITERS  = (ROWS * 8) / 256;   // 16B chunks per stage / threads

    extern __shared__ char smem[];
    const uint32_t sb = smem_u32(smem);
    const int tid  = threadIdx.x;
    const int wid  = tid >> 5;
    const int lane = tid & 31;
    const int wm   = wid & 1;     // 2 warps over M
    const int wn   = wid >> 1;    // 4 warps over N (32 cols each)
    const int bm   = blockIdx.y * CTA_M;
    const int bn   = blockIdx.x * 128;

    float acc[TM][4][4];
    #pragma unroll
    for (int i = 0; i < TM; i++)
        #pragma unroll
        for (int j = 0; j < 4; j++)
            #pragma unroll
            for (int q = 0; q < 4; q++) acc[i][j][q] = 0.0f;

    // per-thread load slots (row, 16B-chunk cc within 128B K-span)
    auto load_stage = [&](int stg, int c) {
        const int kb = c * 64;
        #pragma unroll
        for (int j = 0; j < ITERS; j++) {
            int u   = j * 256 + tid;
            int row = u >> 3, cc = u & 7;
            bool isA = (row < CTA_M);
            uint32_t sa = sb + stg * STAGE
                        + (isA ? row * GPITCH : TILE_A + (row - CTA_M) * GPITCH)
                        + cc * 16;
            const __half* gp = isA ? Ah + (size_t)(bm + row) * EE
                                   : Bh + (size_t)(bn + row - CTA_M) * EE;
            cpasync16(sa, gp + kb + cc * 8);
        }
        CP_COMMIT();
    };

    load_stage(0, 0);
    load_stage(1, 1);

    const uint32_t lrow = (uint32_t)(lane & 15);
    const uint32_t lcol = (uint32_t)((lane >> 4) << 4);

    int stage = 0;
    for (int c = 0; c < 8; c++) {
        if (c < 6)      { load_stage((stage + 2) % 3, c + 2); CP_WAIT(2); }
        else if (c == 6){ CP_WAIT(1); }
        else            { CP_WAIT(0); }
        __syncthreads();

        const uint32_t stg = sb + stage * STAGE;
        const uint32_t abase = stg + (wm * 16 * TM + lrow) * GPITCH + lcol;
        const uint32_t bbase = stg + TILE_A + (wn * 32 + lrow) * GPITCH + lcol;

        uint32_t af[2][TM][4], bf[2][2][4];
        // preload kk = 0
        #pragma unroll
        for (int tm = 0; tm < TM; tm++) ldsm4(af[0][tm], abase + tm * 16 * GPITCH);
        #pragma unroll
        for (int t2 = 0; t2 < 2; t2++)  ldsm4(bf[0][t2], bbase + t2 * 16 * GPITCH);

        #pragma unroll
        for (int kk = 0; kk < 4; kk++) {
            const int cur = kk & 1, nxt = cur ^ 1;
            if (kk < 3) {
                const uint32_t ko = (kk + 1) * 32;
                #pragma unroll
                for (int tm = 0; tm < TM; tm++)
                    ldsm4(af[nxt][tm], abase + tm * 16 * GPITCH + ko);
                #pragma unroll
                for (int t2 = 0; t2 < 2; t2++)
                    ldsm4(bf[nxt][t2], bbase + t2 * 16 * GPITCH + ko);
            }
            #pragma unroll
            for (int tm = 0; tm < TM; tm++)
                #pragma unroll
                for (int tn = 0; tn < 4; tn++) {
                    const int t2 = tn >> 1, hi = tn & 1;
                    mma16816(acc[tm][tn], af[cur][tm],
                             bf[cur][t2][hi], bf[cur][t2][2 + hi]);
                }
        }
        __syncthreads();
        stage = (stage == 2) ? 0 : stage + 1;
    }

    const int r0 = bm + wm * 16 * TM + (lane >> 2);
    const int c0 = bn + wn * 32 + ((lane & 3) << 1);
    #pragma unroll
    for (int tm = 0; tm < TM; tm++) {
        #pragma unroll
        for (int tn = 0; tn < 4; tn++) {
            int row = r0 + tm * 16;
            int col = c0 + tn * 8;
            float bv0 = bias[col], bv1 = bias[col + 1];
            float2 o0 = make_float2(acc[tm][tn][0] + bv0, acc[tm][tn][1] + bv1);
            float2 o1 = make_float2(acc[tm][tn][2] + bv0, acc[tm][tn][3] + bv1);
            *reinterpret_cast<float2*>(Out + (size_t)row * Nst + col)       = o0;
            *reinterpret_cast<float2*>(Out + (size_t)(row + 8) * Nst + col) = o1;
        }
    }
}

// ---------------------------------------------------------------------------
// Sparse tree attention over fused PCS buffer; writes fp16 AO directly.
// One block per (b, n); 8-warp deterministic neighbor scan (ascending m).
// ---------------------------------------------------------------------------
__global__ __launch_bounds__(256) void tree_attn(const int* __restrict__ parent,
                                                 __half* __restrict__ aoh)
{
    const int bn = blockIdx.x;
    const int b  = bn >> 11;
    const int n  = bn & (SS - 1);

    __shared__ int list[8][256];
    __shared__ int cnts[8];

    const int t    = threadIdx.x;
    const int warp = t >> 5;
    const int lane = t & 31;

    const int par_n = parent[b * SS + n];

    int base = 0;
    const int m_lo = warp * 256;
    for (int m0 = m_lo; m0 < m_lo + 256; m0 += 32) {
        int m = m0 + lane;
        bool pred = (m == par_n) || (parent[b * SS + m] == n);
        unsigned bal = __ballot_sync(0xffffffffu, pred);
        int pos = __popc(bal & ((1u << lane) - 1u));
        if (pred) list[warp][base + pos] = m;
        base += __popc(bal);
    }
    if (lane == 0) cnts[warp] = base;
    __syncthreads();

    // PCS row layout: [P(512) | C(512) | S(512)]
    const float* Prow = &g_PCS[(size_t)bn * NPROJ + warp * DD];
    const float p0 = Prow[lane];
    const float p1 = Prow[lane + 32];

    float m_run = -1e30f, l_run = 0.0f, a0 = 0.0f, a1 = 0.0f;
    const float scale = 0.125f;  // 1/sqrt(64)

    for (int w = 0; w < 8; w++) {
        const int cw = cnts[w];
        for (int i = 0; i < cw; i++) {
            int m = list[w][i];
            const float* mbase = &g_PCS[((size_t)b * SS + m) * NPROJ + warp * DD];
            const float* Crow = mbase + 512;
            float part = p0 * Crow[lane] + p1 * Crow[lane + 32];
            #pragma unroll
            for (int off = 16; off; off >>= 1)
                part += __shfl_xor_sync(0xffffffffu, part, off);
            float scr = part * scale;

            float m_new = fmaxf(m_run, scr);
            float corr  = __expf(m_run - m_new);
            float wgt   = __expf(scr - m_new);
            const float* Srow = mbase + 1024;
            a0 = a0 * corr + wgt * Srow[lane];
            a1 = a1 * corr + wgt * Srow[lane + 32];
            l_run = l_run * corr + wgt;
            m_run = m_new;
        }
    }

    const float inv = 1.0f / l_run;
    const size_t obase = (size_t)bn * EE + warp * DD;
    aoh[obase + lane]      = __float2half_rn(a0 * inv);
    aoh[obase + lane + 32] = __float2half_rn(a1 * inv);
}

// ---------------------------------------------------------------------------
extern "C" void kernel_launch(void* const* d_in, const int* in_sizes, int n_in,
                              void* d_out, int out_size)
{
    (void)in_sizes; (void)n_in; (void)out_size;
    const float* x      = (const float*)d_in[0];
    const int*   parent = (const int*)  d_in[1];
    const float* Wp = (const float*)d_in[2];
    const float* bp = (const float*)d_in[3];
    const float* Wc = (const float*)d_in[4];
    const float* bc = (const float*)d_in[5];
    const float* Ws = (const float*)d_in[6];
    const float* bs = (const float*)d_in[7];
    const float* Wo = (const float*)d_in[8];
    const float* bo = (const float*)d_in[9];
    float* out = (float*)d_out;

    float *PCS, *bcat;
    __half *xh, *aoh, *Wt;
    cudaGetSymbolAddress((void**)&PCS,  g_PCS);
    cudaGetSymbolAddress((void**)&bcat, g_bcat);
    cudaGetSymbolAddress((void**)&xh,   g_xh);
    cudaGetSymbolAddress((void**)&aoh,  g_aoh);
    cudaGetSymbolAddress((void**)&Wt,   g_Wt);

    const int SMEM4 = 3 * (256 * GPITCH);   // 110592
    const int SMEM2 = 3 * (192 * GPITCH);   // 82944

    static bool attr_done = false;
    if (!attr_done) {
        cudaFuncSetAttribute(gemm_mma<4>,
            cudaFuncAttributeMaxDynamicSharedMemorySize, SMEM4);
        cudaFuncSetAttribute(gemm_mma<2>,
            cudaFuncAttributeMaxDynamicSharedMemorySize, SMEM2);
        attr_done = true;
    }

    prep_all<<<2048, 256>>>(Wp, Wc, Ws, Wo, bp, bc, bs, x, Wt, bcat, xh);

    // Fused projection GEMM: N = 1536 (Wp|Wc|Ws transposed are contiguous)
    dim3 pgrid(NPROJ / 128, MT / 128);   // (12, 32) = 384 CTAs
    gemm_mma<4><<<pgrid, 256, SMEM4>>>(xh, Wt, bcat, PCS, NPROJ);

    tree_attn<<<MT, 256>>>(parent, aoh);

    dim3 ogrid(EE / 128, MT / 64);       // (4, 64) = 256 CTAs
    gemm_mma<2><<<ogrid, 256, SMEM2>>>(aoh, Wt + 3 * EE * EE, bo, out, EE);
}